// round 5
// baseline (speedup 1.0000x reference)
#include <cuda_runtime.h>
#include <cstdint>

// Problem constants
#define BATCH 2
#define SEQ   2048
#define DIM   1024
#define HEADS 16
#define HD    64
#define MROWS (BATCH * SEQ)      // 4096

// ---------------------------------------------------------------------------
// Scratch (device globals; no allocation allowed)
// q/k/v stored as [B*H][S][HD]; ctx as [B][S][DIM]
// ---------------------------------------------------------------------------
__device__ float g_q[BATCH * HEADS * SEQ * HD];
__device__ float g_k[BATCH * HEADS * SEQ * HD];
__device__ float g_v[BATCH * HEADS * SEQ * HD];
__device__ float g_ctx[BATCH * SEQ * DIM];

// ---------------------------------------------------------------------------
// Kernel 1: fused QKV projection.  y = x @ W + b, written head-split.
// Grid: (N/128, M/128, 3); block 256.  Classic 128x128x8 SGEMM, 8x8 micro.
// ---------------------------------------------------------------------------
__global__ void __launch_bounds__(256) qkv_gemm_kernel(
    const float* __restrict__ X,
    const float* __restrict__ Wq, const float* __restrict__ bq,
    const float* __restrict__ Wk, const float* __restrict__ bk,
    const float* __restrict__ Wv, const float* __restrict__ bv)
{
    const int K = DIM, N = DIM;
    const float* W; const float* bias; float* dst;
    if (blockIdx.z == 0)      { W = Wq; bias = bq; dst = g_q; }
    else if (blockIdx.z == 1) { W = Wk; bias = bk; dst = g_k; }
    else                      { W = Wv; bias = bv; dst = g_v; }

    __shared__ float As[8][128];   // transposed: As[k][m]
    __shared__ float Bs[8][128];   // Bs[k][n]

    const int tid = threadIdx.x;
    const int m0 = blockIdx.y * 128;
    const int n0 = blockIdx.x * 128;
    const int tx = tid & 15;       // 16 col groups of 8
    const int ty = tid >> 4;       // 16 row groups of 8

    const int arow = tid >> 1;            // 0..127
    const int ak4  = (tid & 1) * 4;       // 0 or 4
    const int brow = tid >> 5;            // 0..7
    const int bcol = (tid & 31) * 4;      // 0..124

    const float* Aptr = X + (size_t)(m0 + arow) * K + ak4;
    const float* Bptr = W + (size_t)brow * N + n0 + bcol;

    float acc[8][8];
#pragma unroll
    for (int i = 0; i < 8; i++)
#pragma unroll
        for (int j = 0; j < 8; j++) acc[i][j] = 0.0f;

    for (int k0 = 0; k0 < K; k0 += 8) {
        float4 av = *(const float4*)(Aptr + k0);
        float4 bw = *(const float4*)(Bptr + (size_t)k0 * N);
        As[ak4 + 0][arow] = av.x;
        As[ak4 + 1][arow] = av.y;
        As[ak4 + 2][arow] = av.z;
        As[ak4 + 3][arow] = av.w;
        *(float4*)&Bs[brow][bcol] = bw;
        __syncthreads();

#pragma unroll
        for (int kk = 0; kk < 8; kk++) {
            float a[8], b[8];
            *(float4*)&a[0] = *(const float4*)&As[kk][ty * 8];
            *(float4*)&a[4] = *(const float4*)&As[kk][ty * 8 + 4];
            *(float4*)&b[0] = *(const float4*)&Bs[kk][tx * 8];
            *(float4*)&b[4] = *(const float4*)&Bs[kk][tx * 8 + 4];
#pragma unroll
            for (int i = 0; i < 8; i++)
#pragma unroll
                for (int j = 0; j < 8; j++)
                    acc[i][j] += a[i] * b[j];
        }
        __syncthreads();
    }

    // Epilogue: add bias, scatter to [B*H][S][HD].
    const int ncol = n0 + tx * 8;             // first of 8 contiguous cols
    const int h  = ncol >> 6;                 // head
    const int c0 = ncol & 63;                 // within-head dim (<=56)
    float bb[8];
#pragma unroll
    for (int j = 0; j < 8; j++) bb[j] = bias[ncol + j];

#pragma unroll
    for (int i = 0; i < 8; i++) {
        int m = m0 + ty * 8 + i;
        int b = m >> 11;                      // /SEQ
        int s = m & (SEQ - 1);
        float* op = dst + (((size_t)(b * HEADS + h) * SEQ + s) * HD + c0);
        float4 v0, v1;
        v0.x = acc[i][0] + bb[0]; v0.y = acc[i][1] + bb[1];
        v0.z = acc[i][2] + bb[2]; v0.w = acc[i][3] + bb[3];
        v1.x = acc[i][4] + bb[4]; v1.y = acc[i][5] + bb[5];
        v1.z = acc[i][6] + bb[6]; v1.w = acc[i][7] + bb[7];
        *(float4*)op       = v0;
        *(float4*)(op + 4) = v1;
    }
}

// ---------------------------------------------------------------------------
// Kernel 2: causal flash attention (fp32, online softmax).
// Grid: (S/64, B*H); block 128.  BM=64 q-rows, BN=64 keys/iter, HD=64.
// Dynamic smem: Qs[64][68] + Ks[64][68] + Vs[64][64] + Ps[64][65]
// ---------------------------------------------------------------------------
#define QK_STRIDE 68
#define P_STRIDE  65
#define ATTN_SMEM ((64 * QK_STRIDE * 2 + 64 * 64 + 64 * P_STRIDE) * 4)

__global__ void __launch_bounds__(128) attn_kernel()
{
    extern __shared__ float sm[];
    float* Qs = sm;                          // [d][m] stride 68
    float* Ks = Qs + 64 * QK_STRIDE;         // [d][n] stride 68
    float* Vs = Ks + 64 * QK_STRIDE;         // [n][d] stride 64
    float* Ps = Vs + 64 * 64;                // [n][m] stride 65

    const int bh = blockIdx.y;               // 0..31
    const int q0 = blockIdx.x * 64;
    const float* qptr = g_q + (size_t)bh * SEQ * HD;
    const float* kptr = g_k + (size_t)bh * SEQ * HD;
    const float* vptr = g_v + (size_t)bh * SEQ * HD;

    const int tid = threadIdx.x;
    const int tx = tid & 15;                 // 16 col groups of 4
    const int ty = tid >> 4;                 // 8 row groups of 8

    // Load Q tile transposed into Qs[d][m]
    for (int idx = tid; idx < 64 * 16; idx += 128) {
        int m  = idx >> 4;
        int d4 = (idx & 15) * 4;
        float4 v4 = *(const float4*)(qptr + (size_t)(q0 + m) * HD + d4);
        Qs[(d4 + 0) * QK_STRIDE + m] = v4.x;
        Qs[(d4 + 1) * QK_STRIDE + m] = v4.y;
        Qs[(d4 + 2) * QK_STRIDE + m] = v4.z;
        Qs[(d4 + 3) * QK_STRIDE + m] = v4.w;
    }

    float m_i[8], l_i[8], o[8][4];
#pragma unroll
    for (int i = 0; i < 8; i++) {
        m_i[i] = -1e30f; l_i[i] = 0.0f;
#pragma unroll
        for (int j = 0; j < 4; j++) o[i][j] = 0.0f;
    }

    const int ntiles = blockIdx.x + 1;       // causal: skip future tiles
    const float scale = 0.125f;              // 1/sqrt(64)

    for (int t = 0; t < ntiles; t++) {
        const int n0 = t * 64;
        __syncthreads();   // protect Ks/Vs from previous iter's readers (and Qs on t=0)
        // Load K (transposed) and V tiles
        for (int idx = tid; idx < 64 * 16; idx += 128) {
            int n  = idx >> 4;
            int d4 = (idx & 15) * 4;
            float4 kv = *(const float4*)(kptr + (size_t)(n0 + n) * HD + d4);
            Ks[(d4 + 0) * QK_STRIDE + n] = kv.x;
            Ks[(d4 + 1) * QK_STRIDE + n] = kv.y;
            Ks[(d4 + 2) * QK_STRIDE + n] = kv.z;
            Ks[(d4 + 3) * QK_STRIDE + n] = kv.w;
            float4 vv = *(const float4*)(vptr + (size_t)(n0 + n) * HD + d4);
            *(float4*)&Vs[n * 64 + d4] = vv;
        }
        __syncthreads();

        // S = Q @ K^T  (64x64x64), thread micro-tile 8x4
        float s[8][4];
#pragma unroll
        for (int i = 0; i < 8; i++)
#pragma unroll
            for (int j = 0; j < 4; j++) s[i][j] = 0.0f;

#pragma unroll 8
        for (int kk = 0; kk < 64; kk++) {
            float a[8];
            *(float4*)&a[0] = *(const float4*)&Qs[kk * QK_STRIDE + ty * 8];
            *(float4*)&a[4] = *(const float4*)&Qs[kk * QK_STRIDE + ty * 8 + 4];
            float4 b4 = *(const float4*)&Ks[kk * QK_STRIDE + tx * 4];
#pragma unroll
            for (int i = 0; i < 8; i++) {
                s[i][0] += a[i] * b4.x;
                s[i][1] += a[i] * b4.y;
                s[i][2] += a[i] * b4.z;
                s[i][3] += a[i] * b4.w;
            }
        }

        // scale + causal mask (matches reference: mask value exactly -10000)
#pragma unroll
        for (int i = 0; i < 8; i++) {
            int q = q0 + ty * 8 + i;
#pragma unroll
            for (int j = 0; j < 4; j++) {
                int kc = n0 + tx * 4 + j;
                s[i][j] = (kc <= q) ? s[i][j] * scale : -10000.0f;
            }
        }

        // Online softmax per row (rows shared by 16 lanes with same ty)
#pragma unroll
        for (int i = 0; i < 8; i++) {
            float mx = fmaxf(fmaxf(s[i][0], s[i][1]), fmaxf(s[i][2], s[i][3]));
#pragma unroll
            for (int off = 8; off >= 1; off >>= 1)
                mx = fmaxf(mx, __shfl_xor_sync(0xffffffffu, mx, off));
            float m_new = fmaxf(m_i[i], mx);
            float corr  = __expf(m_i[i] - m_new);
            float ls = 0.0f;
#pragma unroll
            for (int j = 0; j < 4; j++) {
                float p = __expf(s[i][j] - m_new);
                ls += p;
                Ps[(tx * 4 + j) * P_STRIDE + ty * 8 + i] = p;
            }
#pragma unroll
            for (int off = 8; off >= 1; off >>= 1)
                ls += __shfl_xor_sync(0xffffffffu, ls, off);
            l_i[i] = l_i[i] * corr + ls;
            m_i[i] = m_new;
#pragma unroll
            for (int j = 0; j < 4; j++) o[i][j] *= corr;
        }
        __syncthreads();   // publish Ps

        // O += P @ V  (64x64x64)
#pragma unroll 8
        for (int n = 0; n < 64; n++) {
            const float* prow = &Ps[n * P_STRIDE + ty * 8];
            float4 vv = *(const float4*)&Vs[n * 64 + tx * 4];
#pragma unroll
            for (int i = 0; i < 8; i++) {
                float p = prow[i];
                o[i][0] += p * vv.x;
                o[i][1] += p * vv.y;
                o[i][2] += p * vv.z;
                o[i][3] += p * vv.w;
            }
        }
    }

    // Epilogue: normalize, write ctx in [B][S][DIM]
    const int b = bh >> 4;
    const int h = bh & 15;
#pragma unroll
    for (int i = 0; i < 8; i++) {
        float inv = 1.0f / l_i[i];
        int q = q0 + ty * 8 + i;
        float4 v4;
        v4.x = o[i][0] * inv; v4.y = o[i][1] * inv;
        v4.z = o[i][2] * inv; v4.w = o[i][3] * inv;
        *(float4*)&g_ctx[((size_t)(b * SEQ + q)) * DIM + h * HD + tx * 4] = v4;
    }
}

// ---------------------------------------------------------------------------
// Kernel 3: output projection  out = ctx @ Wo + bo   (plain 128x128x8 SGEMM)
// ---------------------------------------------------------------------------
__global__ void __launch_bounds__(256) out_gemm_kernel(
    const float* __restrict__ Wo, const float* __restrict__ bo,
    float* __restrict__ out)
{
    const int K = DIM, N = DIM;
    __shared__ float As[8][128];
    __shared__ float Bs[8][128];

    const int tid = threadIdx.x;
    const int m0 = blockIdx.y * 128;
    const int n0 = blockIdx.x * 128;
    const int tx = tid & 15;
    const int ty = tid >> 4;

    const int arow = tid >> 1;
    const int ak4  = (tid & 1) * 4;
    const int brow = tid >> 5;
    const int bcol = (tid & 31) * 4;

    const float* Aptr = g_ctx + (size_t)(m0 + arow) * K + ak4;
    const float* Bptr = Wo + (size_t)brow * N + n0 + bcol;

    float acc[8][8];
#pragma unroll
    for (int i = 0; i < 8; i++)
#pragma unroll
        for (int j = 0; j < 8; j++) acc[i][j] = 0.0f;

    for (int k0 = 0; k0 < K; k0 += 8) {
        float4 av = *(const float4*)(Aptr + k0);
        float4 bw = *(const float4*)(Bptr + (size_t)k0 * N);
        As[ak4 + 0][arow] = av.x;
        As[ak4 + 1][arow] = av.y;
        As[ak4 + 2][arow] = av.z;
        As[ak4 + 3][arow] = av.w;
        *(float4*)&Bs[brow][bcol] = bw;
        __syncthreads();

#pragma unroll
        for (int kk = 0; kk < 8; kk++) {
            float a[8], b[8];
            *(float4*)&a[0] = *(const float4*)&As[kk][ty * 8];
            *(float4*)&a[4] = *(const float4*)&As[kk][ty * 8 + 4];
            *(float4*)&b[0] = *(const float4*)&Bs[kk][tx * 8];
            *(float4*)&b[4] = *(const float4*)&Bs[kk][tx * 8 + 4];
#pragma unroll
            for (int i = 0; i < 8; i++)
#pragma unroll
                for (int j = 0; j < 8; j++)
                    acc[i][j] += a[i] * b[j];
        }
        __syncthreads();
    }

    float bb[8];
#pragma unroll
    for (int j = 0; j < 8; j++) bb[j] = bo[n0 + tx * 8 + j];

#pragma unroll
    for (int i = 0; i < 8; i++) {
        int m = m0 + ty * 8 + i;
        float* op = out + (size_t)m * N + n0 + tx * 8;
        float4 v0, v1;
        v0.x = acc[i][0] + bb[0]; v0.y = acc[i][1] + bb[1];
        v0.z = acc[i][2] + bb[2]; v0.w = acc[i][3] + bb[3];
        v1.x = acc[i][4] + bb[4]; v1.y = acc[i][5] + bb[5];
        v1.z = acc[i][6] + bb[6]; v1.w = acc[i][7] + bb[7];
        *(float4*)op       = v0;
        *(float4*)(op + 4) = v1;
    }
}

// ---------------------------------------------------------------------------
// Launch
// ---------------------------------------------------------------------------
extern "C" void kernel_launch(void* const* d_in, const int* in_sizes, int n_in,
                              void* d_out, int out_size)
{
    (void)in_sizes; (void)n_in; (void)out_size;
    const float* x  = (const float*)d_in[0];
    const float* Wq = (const float*)d_in[1];
    const float* bq = (const float*)d_in[2];
    const float* Wk = (const float*)d_in[3];
    const float* bk = (const float*)d_in[4];
    const float* Wv = (const float*)d_in[5];
    const float* bv = (const float*)d_in[6];
    const float* Wo = (const float*)d_in[7];
    const float* bo = (const float*)d_in[8];
    float* out = (float*)d_out;

    // Attribute set is not a stream op; safe under graph capture (idempotent).
    cudaFuncSetAttribute(attn_kernel,
                         cudaFuncAttributeMaxDynamicSharedMemorySize, ATTN_SMEM);

    dim3 gq(DIM / 128, MROWS / 128, 3);         // (8, 32, 3)
    qkv_gemm_kernel<<<gq, 256>>>(x, Wq, bq, Wk, bk, Wv, bv);

    dim3 ga(SEQ / 64, BATCH * HEADS);           // (32, 32)
    attn_kernel<<<ga, 128, ATTN_SMEM>>>();

    dim3 go(DIM / 128, MROWS / 128);            // (8, 32)
    out_gemm_kernel<<<go, 256>>>(Wo, bo, out);
}

// round 6
// speedup vs baseline: 1.2193x; 1.2193x over previous
#include <cuda_runtime.h>
#include <cstdint>

// Problem constants
#define BATCH 2
#define SEQ   2048
#define DIM   1024
#define HEADS 16
#define HD    64
#define MROWS (BATCH * SEQ)      // 4096

typedef unsigned long long u64;

// ---------------------------------------------------------------------------
// Packed fp32x2 helpers (Blackwell FFMA2 — ptxas never emits this from C++)
// ---------------------------------------------------------------------------
__device__ __forceinline__ u64 rep2(float x) {
    u64 r;
    asm("mov.b64 %0, {%1, %1};" : "=l"(r) : "r"(__float_as_uint(x)));
    return r;
}
__device__ __forceinline__ u64 pack2(float lo, float hi) {
    u64 r;
    asm("mov.b64 %0, {%1, %2};" : "=l"(r) : "r"(__float_as_uint(lo)), "r"(__float_as_uint(hi)));
    return r;
}
__device__ __forceinline__ void fma2(u64& d, u64 a, u64 b) {
    asm("fma.rn.f32x2 %0, %1, %2, %0;" : "+l"(d) : "l"(a), "l"(b));
}
__device__ __forceinline__ void mul2(u64& d, u64 a) {
    asm("mul.rn.f32x2 %0, %0, %1;" : "+l"(d) : "l"(a));
}
__device__ __forceinline__ float lo2(u64 v) { return __uint_as_float((unsigned)(v & 0xffffffffull)); }
__device__ __forceinline__ float hi2(u64 v) { return __uint_as_float((unsigned)(v >> 32)); }

// ---------------------------------------------------------------------------
// Scratch (device globals; no allocation allowed)
// q/k/v stored as [B*H][S][HD]; ctx as [B][S][DIM]
// ---------------------------------------------------------------------------
__device__ float g_q[BATCH * HEADS * SEQ * HD];
__device__ float g_k[BATCH * HEADS * SEQ * HD];
__device__ float g_v[BATCH * HEADS * SEQ * HD];
__device__ float g_ctx[BATCH * SEQ * DIM];

// ---------------------------------------------------------------------------
// Kernel 1: fused QKV projection, FFMA2 + double-buffered smem.
// 128x128 tile, BK=8, 256 threads. Micro-tile: rows {ty*4, 64+ty*4} x
// cols {tx*4, 64+tx*4}; cols packed as f32x2 pairs, rows replicated.
// ---------------------------------------------------------------------------
#define BK 8
__global__ void __launch_bounds__(256, 2) qkv_gemm_kernel(
    const float* __restrict__ X,
    const float* __restrict__ Wq, const float* __restrict__ bq,
    const float* __restrict__ Wk, const float* __restrict__ bk,
    const float* __restrict__ Wv, const float* __restrict__ bv)
{
    const int K = DIM, N = DIM;
    const float* W; const float* bias; float* dst;
    if (blockIdx.z == 0)      { W = Wq; bias = bq; dst = g_q; }
    else if (blockIdx.z == 1) { W = Wk; bias = bk; dst = g_k; }
    else                      { W = Wv; bias = bv; dst = g_v; }

    __shared__ float As[2][BK][128];   // transposed: As[k][m]
    __shared__ float Bs[2][BK][128];   // Bs[k][n]

    const int tid = threadIdx.x;
    const int m0 = blockIdx.y * 128;
    const int n0 = blockIdx.x * 128;
    const int tx = tid & 15;
    const int ty = tid >> 4;

    const int arow = tid >> 1;
    const int ak4  = (tid & 1) * 4;
    const int brow = tid >> 5;
    const int bcol = (tid & 31) * 4;

    const float* Aptr = X + (size_t)(m0 + arow) * K + ak4;
    const float* Bptr = W + (size_t)brow * N + n0 + bcol;

    u64 acc[8][4];
#pragma unroll
    for (int i = 0; i < 8; i++)
#pragma unroll
        for (int j = 0; j < 4; j++) acc[i][j] = 0ull;

    // Prologue: load tile 0
    float4 av = *(const float4*)Aptr;
    float4 bw = *(const float4*)Bptr;
    As[0][ak4 + 0][arow] = av.x;
    As[0][ak4 + 1][arow] = av.y;
    As[0][ak4 + 2][arow] = av.z;
    As[0][ak4 + 3][arow] = av.w;
    *(float4*)&Bs[0][brow][bcol] = bw;
    __syncthreads();

    int buf = 0;
    for (int k0 = 0; k0 < K; k0 += BK) {
        const bool more = (k0 + BK) < K;
        if (more) {
            av = *(const float4*)(Aptr + k0 + BK);
            bw = *(const float4*)(Bptr + (size_t)(k0 + BK) * N);
        }

#pragma unroll
        for (int kk = 0; kk < BK; kk++) {
            float4 a0 = *(const float4*)&As[buf][kk][ty * 4];
            float4 a1 = *(const float4*)&As[buf][kk][64 + ty * 4];
            u64 b2[4];
            b2[0] = *(const u64*)&Bs[buf][kk][tx * 4];
            b2[1] = *(const u64*)&Bs[buf][kk][tx * 4 + 2];
            b2[2] = *(const u64*)&Bs[buf][kk][64 + tx * 4];
            b2[3] = *(const u64*)&Bs[buf][kk][64 + tx * 4 + 2];
            u64 ar[8];
            ar[0] = rep2(a0.x); ar[1] = rep2(a0.y);
            ar[2] = rep2(a0.z); ar[3] = rep2(a0.w);
            ar[4] = rep2(a1.x); ar[5] = rep2(a1.y);
            ar[6] = rep2(a1.z); ar[7] = rep2(a1.w);
#pragma unroll
            for (int i = 0; i < 8; i++)
#pragma unroll
                for (int j = 0; j < 4; j++)
                    fma2(acc[i][j], ar[i], b2[j]);
        }

        if (more) {
            As[buf ^ 1][ak4 + 0][arow] = av.x;
            As[buf ^ 1][ak4 + 1][arow] = av.y;
            As[buf ^ 1][ak4 + 2][arow] = av.z;
            As[buf ^ 1][ak4 + 3][arow] = av.w;
            *(float4*)&Bs[buf ^ 1][brow][bcol] = bw;
        }
        __syncthreads();
        buf ^= 1;
    }

    // Epilogue: add bias, scatter to [B*H][S][HD].
    const int c0 = n0 + tx * 4;               // first col of group 0 (4-aligned, within one head)
    const int h0 = c0 >> 6;
    const int cc = c0 & 63;
    float4 bb0 = *(const float4*)&bias[c0];
    float4 bb1 = *(const float4*)&bias[c0 + 64];

#pragma unroll
    for (int g = 0; g < 2; g++) {
#pragma unroll
        for (int i = 0; i < 4; i++) {
            const int ii = g * 4 + i;
            const int m = m0 + g * 64 + ty * 4 + i;
            const int b = m >> 11;
            const int s = m & (SEQ - 1);
            float4 v0, v1;
            v0.x = lo2(acc[ii][0]) + bb0.x; v0.y = hi2(acc[ii][0]) + bb0.y;
            v0.z = lo2(acc[ii][1]) + bb0.z; v0.w = hi2(acc[ii][1]) + bb0.w;
            v1.x = lo2(acc[ii][2]) + bb1.x; v1.y = hi2(acc[ii][2]) + bb1.y;
            v1.z = lo2(acc[ii][3]) + bb1.z; v1.w = hi2(acc[ii][3]) + bb1.w;
            *(float4*)(dst + (((size_t)(b * HEADS + h0)     * SEQ + s) * HD + cc)) = v0;
            *(float4*)(dst + (((size_t)(b * HEADS + h0 + 1) * SEQ + s) * HD + cc)) = v1;
        }
    }
}

// ---------------------------------------------------------------------------
// Kernel 2: causal flash attention, fp32 online softmax, FFMA2 inner GEMMs.
// Grid: (S/64, B*H); block 128.  BM=64, BN=64, HD=64.
// Row-pairs packed as f32x2 (acc pairs rows 2i2/2i2+1), cols replicated.
// ---------------------------------------------------------------------------
#define QK_STRIDE 68
#define P2_STRIDE 33   // u64 stride for packed P
#define ATTN_SMEM ((64 * QK_STRIDE * 2 + 64 * 64) * 4 + 64 * P2_STRIDE * 8)

__global__ void __launch_bounds__(128, 3) attn_kernel()
{
    extern __shared__ float sm[];
    float* Qs = sm;                           // [d][m] stride 68
    float* Ks = Qs + 64 * QK_STRIDE;          // [d][n] stride 68
    float* Vs = Ks + 64 * QK_STRIDE;          // [n][d] stride 64
    u64*   Ps2 = (u64*)(Vs + 64 * 64);        // [n][m/2] stride 33 (8B aligned)

    const int bh = blockIdx.y;                // 0..31
    // Heaviest causal tiles first (better tail behavior)
    const int q0 = (gridDim.x - 1 - blockIdx.x) * 64;
    const float* qptr = g_q + (size_t)bh * SEQ * HD;
    const float* kptr = g_k + (size_t)bh * SEQ * HD;
    const float* vptr = g_v + (size_t)bh * SEQ * HD;

    const int tid = threadIdx.x;
    const int tx = tid & 15;                  // 16 col groups of 4
    const int ty = tid >> 4;                  // 8 row groups of 8

    // Load Q tile transposed into Qs[d][m]
    for (int idx = tid; idx < 64 * 16; idx += 128) {
        int m  = idx >> 4;
        int d4 = (idx & 15) * 4;
        float4 v4 = *(const float4*)(qptr + (size_t)(q0 + m) * HD + d4);
        Qs[(d4 + 0) * QK_STRIDE + m] = v4.x;
        Qs[(d4 + 1) * QK_STRIDE + m] = v4.y;
        Qs[(d4 + 2) * QK_STRIDE + m] = v4.z;
        Qs[(d4 + 3) * QK_STRIDE + m] = v4.w;
    }

    float m_i[8], l_i[8];
    u64 o2[4][4];
#pragma unroll
    for (int i = 0; i < 8; i++) { m_i[i] = -1e30f; l_i[i] = 0.0f; }
#pragma unroll
    for (int i2 = 0; i2 < 4; i2++)
#pragma unroll
        for (int j = 0; j < 4; j++) o2[i2][j] = 0ull;

    const int ntiles = q0 / 64 + 1;           // causal: skip future tiles
    const float scale = 0.125f;               // 1/sqrt(64)

    for (int t = 0; t < ntiles; t++) {
        const int n0 = t * 64;
        __syncthreads();   // protect Ks/Vs from previous iter's readers (and Qs on t=0)
        for (int idx = tid; idx < 64 * 16; idx += 128) {
            int n  = idx >> 4;
            int d4 = (idx & 15) * 4;
            float4 kv = *(const float4*)(kptr + (size_t)(n0 + n) * HD + d4);
            Ks[(d4 + 0) * QK_STRIDE + n] = kv.x;
            Ks[(d4 + 1) * QK_STRIDE + n] = kv.y;
            Ks[(d4 + 2) * QK_STRIDE + n] = kv.z;
            Ks[(d4 + 3) * QK_STRIDE + n] = kv.w;
            float4 vv = *(const float4*)(vptr + (size_t)(n0 + n) * HD + d4);
            *(float4*)&Vs[n * 64 + d4] = vv;
        }
        __syncthreads();

        // S = Q @ K^T  (64x64x64): rows packed in pairs, cols replicated
        u64 s2[4][4];
#pragma unroll
        for (int i2 = 0; i2 < 4; i2++)
#pragma unroll
            for (int j = 0; j < 4; j++) s2[i2][j] = 0ull;

#pragma unroll 8
        for (int kk = 0; kk < 64; kk++) {
            u64 ap[4];
#pragma unroll
            for (int i2 = 0; i2 < 4; i2++)
                ap[i2] = *(const u64*)&Qs[kk * QK_STRIDE + ty * 8 + 2 * i2];
            float4 b4 = *(const float4*)&Ks[kk * QK_STRIDE + tx * 4];
            u64 br[4];
            br[0] = rep2(b4.x); br[1] = rep2(b4.y);
            br[2] = rep2(b4.z); br[3] = rep2(b4.w);
#pragma unroll
            for (int i2 = 0; i2 < 4; i2++)
#pragma unroll
                for (int j = 0; j < 4; j++)
                    fma2(s2[i2][j], ap[i2], br[j]);
        }

        // Unpack, scale + causal mask (exactly -10000, matching reference)
        float s[8][4];
#pragma unroll
        for (int i2 = 0; i2 < 4; i2++)
#pragma unroll
            for (int j = 0; j < 4; j++) {
                s[2 * i2 + 0][j] = lo2(s2[i2][j]);
                s[2 * i2 + 1][j] = hi2(s2[i2][j]);
            }
#pragma unroll
        for (int i = 0; i < 8; i++) {
            int q = q0 + ty * 8 + i;
#pragma unroll
            for (int j = 0; j < 4; j++) {
                int kc = n0 + tx * 4 + j;
                s[i][j] = (kc <= q) ? s[i][j] * scale : -10000.0f;
            }
        }

        // Online softmax per row (rows shared by 16 lanes with same ty)
        float corr[8];
#pragma unroll
        for (int i = 0; i < 8; i++) {
            float mx = fmaxf(fmaxf(s[i][0], s[i][1]), fmaxf(s[i][2], s[i][3]));
#pragma unroll
            for (int off = 8; off >= 1; off >>= 1)
                mx = fmaxf(mx, __shfl_xor_sync(0xffffffffu, mx, off));
            float m_new = fmaxf(m_i[i], mx);
            corr[i] = __expf(m_i[i] - m_new);
            float ls = 0.0f;
#pragma unroll
            for (int j = 0; j < 4; j++) {
                float p = __expf(s[i][j] - m_new);
                s[i][j] = p;                  // reuse s as P
                ls += p;
            }
#pragma unroll
            for (int off = 8; off >= 1; off >>= 1)
                ls += __shfl_xor_sync(0xffffffffu, ls, off);
            l_i[i] = l_i[i] * corr[i] + ls;
            m_i[i] = m_new;
        }

        // Publish P packed as row-pairs: Ps2[n][m/2]
#pragma unroll
        for (int j = 0; j < 4; j++)
#pragma unroll
            for (int i2 = 0; i2 < 4; i2++)
                Ps2[(tx * 4 + j) * P2_STRIDE + ty * 4 + i2] =
                    pack2(s[2 * i2][j], s[2 * i2 + 1][j]);

        // Rescale O accumulators by packed corr
#pragma unroll
        for (int i2 = 0; i2 < 4; i2++) {
            u64 c2 = pack2(corr[2 * i2], corr[2 * i2 + 1]);
#pragma unroll
            for (int j = 0; j < 4; j++) mul2(o2[i2][j], c2);
        }
        __syncthreads();   // Ps2 visible to all

        // O += P @ V  (64x64x64)
#pragma unroll 4
        for (int n = 0; n < 64; n++) {
            u64 pp[4];
#pragma unroll
            for (int i2 = 0; i2 < 4; i2++)
                pp[i2] = Ps2[n * P2_STRIDE + ty * 4 + i2];
            float4 v4 = *(const float4*)&Vs[n * 64 + tx * 4];
            u64 vr[4];
            vr[0] = rep2(v4.x); vr[1] = rep2(v4.y);
            vr[2] = rep2(v4.z); vr[3] = rep2(v4.w);
#pragma unroll
            for (int i2 = 0; i2 < 4; i2++)
#pragma unroll
                for (int j = 0; j < 4; j++)
                    fma2(o2[i2][j], pp[i2], vr[j]);
        }
    }

    // Epilogue: normalize, write ctx in [B][S][DIM]
    const int b = bh >> 4;
    const int h = bh & 15;
#pragma unroll
    for (int i2 = 0; i2 < 4; i2++) {
#pragma unroll
        for (int half = 0; half < 2; half++) {
            const int i = 2 * i2 + half;
            const float inv = 1.0f / l_i[i];
            const int q = q0 + ty * 8 + i;
            float4 v4;
            v4.x = (half ? hi2(o2[i2][0]) : lo2(o2[i2][0])) * inv;
            v4.y = (half ? hi2(o2[i2][1]) : lo2(o2[i2][1])) * inv;
            v4.z = (half ? hi2(o2[i2][2]) : lo2(o2[i2][2])) * inv;
            v4.w = (half ? hi2(o2[i2][3]) : lo2(o2[i2][3])) * inv;
            *(float4*)&g_ctx[((size_t)(b * SEQ + q)) * DIM + h * HD + tx * 4] = v4;
        }
    }
}

// ---------------------------------------------------------------------------
// Kernel 3: output projection (same FFMA2 SGEMM, plain output)
// ---------------------------------------------------------------------------
__global__ void __launch_bounds__(256, 2) out_gemm_kernel(
    const float* __restrict__ Wo, const float* __restrict__ bo,
    float* __restrict__ out)
{
    const int K = DIM, N = DIM;
    __shared__ float As[2][BK][128];
    __shared__ float Bs[2][BK][128];

    const int tid = threadIdx.x;
    const int m0 = blockIdx.y * 128;
    const int n0 = blockIdx.x * 128;
    const int tx = tid & 15;
    const int ty = tid >> 4;

    const int arow = tid >> 1;
    const int ak4  = (tid & 1) * 4;
    const int brow = tid >> 5;
    const int bcol = (tid & 31) * 4;

    const float* Aptr = g_ctx + (size_t)(m0 + arow) * K + ak4;
    const float* Bptr = Wo + (size_t)brow * N + n0 + bcol;

    u64 acc[8][4];
#pragma unroll
    for (int i = 0; i < 8; i++)
#pragma unroll
        for (int j = 0; j < 4; j++) acc[i][j] = 0ull;

    float4 av = *(const float4*)Aptr;
    float4 bw = *(const float4*)Bptr;
    As[0][ak4 + 0][arow] = av.x;
    As[0][ak4 + 1][arow] = av.y;
    As[0][ak4 + 2][arow] = av.z;
    As[0][ak4 + 3][arow] = av.w;
    *(float4*)&Bs[0][brow][bcol] = bw;
    __syncthreads();

    int buf = 0;
    for (int k0 = 0; k0 < K; k0 += BK) {
        const bool more = (k0 + BK) < K;
        if (more) {
            av = *(const float4*)(Aptr + k0 + BK);
            bw = *(const float4*)(Bptr + (size_t)(k0 + BK) * N);
        }

#pragma unroll
        for (int kk = 0; kk < BK; kk++) {
            float4 a0 = *(const float4*)&As[buf][kk][ty * 4];
            float4 a1 = *(const float4*)&As[buf][kk][64 + ty * 4];
            u64 b2[4];
            b2[0] = *(const u64*)&Bs[buf][kk][tx * 4];
            b2[1] = *(const u64*)&Bs[buf][kk][tx * 4 + 2];
            b2[2] = *(const u64*)&Bs[buf][kk][64 + tx * 4];
            b2[3] = *(const u64*)&Bs[buf][kk][64 + tx * 4 + 2];
            u64 ar[8];
            ar[0] = rep2(a0.x); ar[1] = rep2(a0.y);
            ar[2] = rep2(a0.z); ar[3] = rep2(a0.w);
            ar[4] = rep2(a1.x); ar[5] = rep2(a1.y);
            ar[6] = rep2(a1.z); ar[7] = rep2(a1.w);
#pragma unroll
            for (int i = 0; i < 8; i++)
#pragma unroll
                for (int j = 0; j < 4; j++)
                    fma2(acc[i][j], ar[i], b2[j]);
        }

        if (more) {
            As[buf ^ 1][ak4 + 0][arow] = av.x;
            As[buf ^ 1][ak4 + 1][arow] = av.y;
            As[buf ^ 1][ak4 + 2][arow] = av.z;
            As[buf ^ 1][ak4 + 3][arow] = av.w;
            *(float4*)&Bs[buf ^ 1][brow][bcol] = bw;
        }
        __syncthreads();
        buf ^= 1;
    }

    const int c0 = n0 + tx * 4;
    float4 bb0 = *(const float4*)&bo[c0];
    float4 bb1 = *(const float4*)&bo[c0 + 64];

#pragma unroll
    for (int g = 0; g < 2; g++) {
#pragma unroll
        for (int i = 0; i < 4; i++) {
            const int ii = g * 4 + i;
            const int m = m0 + g * 64 + ty * 4 + i;
            float4 v0, v1;
            v0.x = lo2(acc[ii][0]) + bb0.x; v0.y = hi2(acc[ii][0]) + bb0.y;
            v0.z = lo2(acc[ii][1]) + bb0.z; v0.w = hi2(acc[ii][1]) + bb0.w;
            v1.x = lo2(acc[ii][2]) + bb1.x; v1.y = hi2(acc[ii][2]) + bb1.y;
            v1.z = lo2(acc[ii][3]) + bb1.z; v1.w = hi2(acc[ii][3]) + bb1.w;
            *(float4*)(out + (size_t)m * N + c0)      = v0;
            *(float4*)(out + (size_t)m * N + c0 + 64) = v1;
        }
    }
}

// ---------------------------------------------------------------------------
// Launch
// ---------------------------------------------------------------------------
extern "C" void kernel_launch(void* const* d_in, const int* in_sizes, int n_in,
                              void* d_out, int out_size)
{
    (void)in_sizes; (void)n_in; (void)out_size;
    const float* x  = (const float*)d_in[0];
    const float* Wq = (const float*)d_in[1];
    const float* bq = (const float*)d_in[2];
    const float* Wk = (const float*)d_in[3];
    const float* bk = (const float*)d_in[4];
    const float* Wv = (const float*)d_in[5];
    const float* bv = (const float*)d_in[6];
    const float* Wo = (const float*)d_in[7];
    const float* bo = (const float*)d_in[8];
    float* out = (float*)d_out;

    cudaFuncSetAttribute(attn_kernel,
                         cudaFuncAttributeMaxDynamicSharedMemorySize, ATTN_SMEM);

    dim3 gq(DIM / 128, MROWS / 128, 3);         // (8, 32, 3)
    qkv_gemm_kernel<<<gq, 256>>>(x, Wq, bq, Wk, bk, Wv, bv);

    dim3 ga(SEQ / 64, BATCH * HEADS);           // (32, 32)
    attn_kernel<<<ga, 128, ATTN_SMEM>>>();

    dim3 go(DIM / 128, MROWS / 128);            // (8, 32)
    out_gemm_kernel<<<go, 256>>>(Wo, bo, out);
}

// round 9
// speedup vs baseline: 1.2272x; 1.0065x over previous
#include <cuda_runtime.h>
#include <cstdint>

// Problem constants
#define BATCH 2
#define SEQ   2048
#define DIM   1024
#define HEADS 16
#define HD    64
#define MROWS (BATCH * SEQ)      // 4096

typedef unsigned long long u64;

// ---------------------------------------------------------------------------
// Packed fp32x2 helpers (Blackwell FFMA2 — ptxas never emits this from C++)
// ---------------------------------------------------------------------------
__device__ __forceinline__ u64 rep2(float x) {
    u64 r;
    asm("mov.b64 %0, {%1, %1};" : "=l"(r) : "r"(__float_as_uint(x)));
    return r;
}
__device__ __forceinline__ u64 pack2(float lo, float hi) {
    u64 r;
    asm("mov.b64 %0, {%1, %2};" : "=l"(r) : "r"(__float_as_uint(lo)), "r"(__float_as_uint(hi)));
    return r;
}
__device__ __forceinline__ void fma2(u64& d, u64 a, u64 b) {
    asm("fma.rn.f32x2 %0, %1, %2, %0;" : "+l"(d) : "l"(a), "l"(b));
}
__device__ __forceinline__ void mul2(u64& d, u64 a) {
    asm("mul.rn.f32x2 %0, %0, %1;" : "+l"(d) : "l"(a));
}
__device__ __forceinline__ float lo2(u64 v) { return __uint_as_float((unsigned)(v & 0xffffffffull)); }
__device__ __forceinline__ float hi2(u64 v) { return __uint_as_float((unsigned)(v >> 32)); }

// ---------------------------------------------------------------------------
// Scratch (device globals; no allocation allowed)
// q/k/v stored as [B*H][S][HD]; ctx as [B][S][DIM]
// ---------------------------------------------------------------------------
__device__ float g_q[BATCH * HEADS * SEQ * HD];
__device__ float g_k[BATCH * HEADS * SEQ * HD];
__device__ float g_v[BATCH * HEADS * SEQ * HD];
__device__ float g_ctx[BATCH * SEQ * DIM];

// ---------------------------------------------------------------------------
// Kernel 1: fused QKV projection, FFMA2 + double-buffered smem.
// 128x128 tile, BK=8, 256 threads. Micro-tile: rows {ty*4, 64+ty*4} x
// cols {tx*4, 64+tx*4}; cols packed as f32x2 pairs, rows replicated.
// ---------------------------------------------------------------------------
#define BK 8
__global__ void __launch_bounds__(256, 2) qkv_gemm_kernel(
    const float* __restrict__ X,
    const float* __restrict__ Wq, const float* __restrict__ bq,
    const float* __restrict__ Wk, const float* __restrict__ bk,
    const float* __restrict__ Wv, const float* __restrict__ bv)
{
    const int K = DIM, N = DIM;
    const float* W; const float* bias; float* dst;
    if (blockIdx.z == 0)      { W = Wq; bias = bq; dst = g_q; }
    else if (blockIdx.z == 1) { W = Wk; bias = bk; dst = g_k; }
    else                      { W = Wv; bias = bv; dst = g_v; }

    __shared__ float As[2][BK][128];   // transposed: As[k][m]
    __shared__ float Bs[2][BK][128];   // Bs[k][n]

    const int tid = threadIdx.x;
    const int m0 = blockIdx.y * 128;
    const int n0 = blockIdx.x * 128;
    const int tx = tid & 15;
    const int ty = tid >> 4;

    const int arow = tid >> 1;
    const int ak4  = (tid & 1) * 4;
    const int brow = tid >> 5;
    const int bcol = (tid & 31) * 4;

    const float* Aptr = X + (size_t)(m0 + arow) * K + ak4;
    const float* Bptr = W + (size_t)brow * N + n0 + bcol;

    u64 acc[8][4];
#pragma unroll
    for (int i = 0; i < 8; i++)
#pragma unroll
        for (int j = 0; j < 4; j++) acc[i][j] = 0ull;

    // Prologue: load tile 0
    float4 av = *(const float4*)Aptr;
    float4 bw = *(const float4*)Bptr;
    As[0][ak4 + 0][arow] = av.x;
    As[0][ak4 + 1][arow] = av.y;
    As[0][ak4 + 2][arow] = av.z;
    As[0][ak4 + 3][arow] = av.w;
    *(float4*)&Bs[0][brow][bcol] = bw;
    __syncthreads();

    int buf = 0;
    for (int k0 = 0; k0 < K; k0 += BK) {
        const bool more = (k0 + BK) < K;
        if (more) {
            av = *(const float4*)(Aptr + k0 + BK);
            bw = *(const float4*)(Bptr + (size_t)(k0 + BK) * N);
        }

#pragma unroll
        for (int kk = 0; kk < BK; kk++) {
            float4 a0 = *(const float4*)&As[buf][kk][ty * 4];
            float4 a1 = *(const float4*)&As[buf][kk][64 + ty * 4];
            u64 b2[4];
            b2[0] = *(const u64*)&Bs[buf][kk][tx * 4];
            b2[1] = *(const u64*)&Bs[buf][kk][tx * 4 + 2];
            b2[2] = *(const u64*)&Bs[buf][kk][64 + tx * 4];
            b2[3] = *(const u64*)&Bs[buf][kk][64 + tx * 4 + 2];
            u64 ar[8];
            ar[0] = rep2(a0.x); ar[1] = rep2(a0.y);
            ar[2] = rep2(a0.z); ar[3] = rep2(a0.w);
            ar[4] = rep2(a1.x); ar[5] = rep2(a1.y);
            ar[6] = rep2(a1.z); ar[7] = rep2(a1.w);
#pragma unroll
            for (int i = 0; i < 8; i++)
#pragma unroll
                for (int j = 0; j < 4; j++)
                    fma2(acc[i][j], ar[i], b2[j]);
        }

        if (more) {
            As[buf ^ 1][ak4 + 0][arow] = av.x;
            As[buf ^ 1][ak4 + 1][arow] = av.y;
            As[buf ^ 1][ak4 + 2][arow] = av.z;
            As[buf ^ 1][ak4 + 3][arow] = av.w;
            *(float4*)&Bs[buf ^ 1][brow][bcol] = bw;
        }
        __syncthreads();
        buf ^= 1;
    }

    // Epilogue: add bias, scatter to [B*H][S][HD].
    const int c0 = n0 + tx * 4;               // first col of group 0 (4-aligned, within one head)
    const int h0 = c0 >> 6;
    const int cc = c0 & 63;
    float4 bb0 = *(const float4*)&bias[c0];
    float4 bb1 = *(const float4*)&bias[c0 + 64];

#pragma unroll
    for (int g = 0; g < 2; g++) {
#pragma unroll
        for (int i = 0; i < 4; i++) {
            const int ii = g * 4 + i;
            const int m = m0 + g * 64 + ty * 4 + i;
            const int b = m >> 11;
            const int s = m & (SEQ - 1);
            float4 v0, v1;
            v0.x = lo2(acc[ii][0]) + bb0.x; v0.y = hi2(acc[ii][0]) + bb0.y;
            v0.z = lo2(acc[ii][1]) + bb0.z; v0.w = hi2(acc[ii][1]) + bb0.w;
            v1.x = lo2(acc[ii][2]) + bb1.x; v1.y = hi2(acc[ii][2]) + bb1.y;
            v1.z = lo2(acc[ii][3]) + bb1.z; v1.w = hi2(acc[ii][3]) + bb1.w;
            *(float4*)(dst + (((size_t)(b * HEADS + h0)     * SEQ + s) * HD + cc)) = v0;
            *(float4*)(dst + (((size_t)(b * HEADS + h0 + 1) * SEQ + s) * HD + cc)) = v1;
        }
    }
}

// ---------------------------------------------------------------------------
// Kernel 2: causal flash attention, fp32 online softmax, FFMA2 inner GEMMs.
// Grid: (S/64, B*H); block 128.  BM=64, BN=64, HD=64.
// Row-pairs packed as f32x2 (acc pairs rows 2i2/2i2+1), cols replicated.
// ---------------------------------------------------------------------------
#define QK_STRIDE 68
#define P2_STRIDE 33   // u64 stride for packed P
#define ATTN_SMEM ((64 * QK_STRIDE * 2 + 64 * 64) * 4 + 64 * P2_STRIDE * 8)

__global__ void __launch_bounds__(128, 3) attn_kernel()
{
    extern __shared__ float sm[];
    float* Qs = sm;                           // [d][m] stride 68
    float* Ks = Qs + 64 * QK_STRIDE;          // [d][n] stride 68
    float* Vs = Ks + 64 * QK_STRIDE;          // [n][d] stride 64
    u64*   Ps2 = (u64*)(Vs + 64 * 64);        // [n][m/2] stride 33 (8B aligned)

    const int bh = blockIdx.y;                // 0..31
    // Heaviest causal tiles first (better tail behavior)
    const int q0 = (gridDim.x - 1 - blockIdx.x) * 64;
    const float* qptr = g_q + (size_t)bh * SEQ * HD;
    const float* kptr = g_k + (size_t)bh * SEQ * HD;
    const float* vptr = g_v + (size_t)bh * SEQ * HD;

    const int tid = threadIdx.x;
    const int tx = tid & 15;                  // 16 col groups of 4
    const int ty = tid >> 4;                  // 8 row groups of 8

    // Load Q tile transposed into Qs[d][m]
    for (int idx = tid; idx < 64 * 16; idx += 128) {
        int m  = idx >> 4;
        int d4 = (idx & 15) * 4;
        float4 v4 = *(const float4*)(qptr + (size_t)(q0 + m) * HD + d4);
        Qs[(d4 + 0) * QK_STRIDE + m] = v4.x;
        Qs[(d4 + 1) * QK_STRIDE + m] = v4.y;
        Qs[(d4 + 2) * QK_STRIDE + m] = v4.z;
        Qs[(d4 + 3) * QK_STRIDE + m] = v4.w;
    }

    float m_i[8], l_i[8];
    u64 o2[4][4];
#pragma unroll
    for (int i = 0; i < 8; i++) { m_i[i] = -1e30f; l_i[i] = 0.0f; }
#pragma unroll
    for (int i2 = 0; i2 < 4; i2++)
#pragma unroll
        for (int j = 0; j < 4; j++) o2[i2][j] = 0ull;

    const int ntiles = q0 / 64 + 1;           // causal: skip future tiles
    const float scale = 0.125f;               // 1/sqrt(64)

    for (int t = 0; t < ntiles; t++) {
        const int n0 = t * 64;
        __syncthreads();   // protect Ks/Vs from previous iter's readers (and Qs on t=0)
        for (int idx = tid; idx < 64 * 16; idx += 128) {
            int n  = idx >> 4;
            int d4 = (idx & 15) * 4;
            float4 kv = *(const float4*)(kptr + (size_t)(n0 + n) * HD + d4);
            Ks[(d4 + 0) * QK_STRIDE + n] = kv.x;
            Ks[(d4 + 1) * QK_STRIDE + n] = kv.y;
            Ks[(d4 + 2) * QK_STRIDE + n] = kv.z;
            Ks[(d4 + 3) * QK_STRIDE + n] = kv.w;
            float4 vv = *(const float4*)(vptr + (size_t)(n0 + n) * HD + d4);
            *(float4*)&Vs[n * 64 + d4] = vv;
        }
        __syncthreads();

        // S = Q @ K^T  (64x64x64): rows packed in pairs, cols replicated
        u64 s2[4][4];
#pragma unroll
        for (int i2 = 0; i2 < 4; i2++)
#pragma unroll
            for (int j = 0; j < 4; j++) s2[i2][j] = 0ull;

#pragma unroll 8
        for (int kk = 0; kk < 64; kk++) {
            u64 ap[4];
#pragma unroll
            for (int i2 = 0; i2 < 4; i2++)
                ap[i2] = *(const u64*)&Qs[kk * QK_STRIDE + ty * 8 + 2 * i2];
            float4 b4 = *(const float4*)&Ks[kk * QK_STRIDE + tx * 4];
            u64 br[4];
            br[0] = rep2(b4.x); br[1] = rep2(b4.y);
            br[2] = rep2(b4.z); br[3] = rep2(b4.w);
#pragma unroll
            for (int i2 = 0; i2 < 4; i2++)
#pragma unroll
                for (int j = 0; j < 4; j++)
                    fma2(s2[i2][j], ap[i2], br[j]);
        }

        // Unpack, scale + causal mask (exactly -10000, matching reference)
        float s[8][4];
#pragma unroll
        for (int i2 = 0; i2 < 4; i2++)
#pragma unroll
            for (int j = 0; j < 4; j++) {
                s[2 * i2 + 0][j] = lo2(s2[i2][j]);
                s[2 * i2 + 1][j] = hi2(s2[i2][j]);
            }
#pragma unroll
        for (int i = 0; i < 8; i++) {
            int q = q0 + ty * 8 + i;
#pragma unroll
            for (int j = 0; j < 4; j++) {
                int kc = n0 + tx * 4 + j;
                s[i][j] = (kc <= q) ? s[i][j] * scale : -10000.0f;
            }
        }

        // Online softmax per row (rows shared by 16 lanes with same ty)
        float corr[8];
#pragma unroll
        for (int i = 0; i < 8; i++) {
            float mx = fmaxf(fmaxf(s[i][0], s[i][1]), fmaxf(s[i][2], s[i][3]));
#pragma unroll
            for (int off = 8; off >= 1; off >>= 1)
                mx = fmaxf(mx, __shfl_xor_sync(0xffffffffu, mx, off));
            float m_new = fmaxf(m_i[i], mx);
            corr[i] = __expf(m_i[i] - m_new);
            float ls = 0.0f;
#pragma unroll
            for (int j = 0; j < 4; j++) {
                float p = __expf(s[i][j] - m_new);
                s[i][j] = p;                  // reuse s as P
                ls += p;
            }
#pragma unroll
            for (int off = 8; off >= 1; off >>= 1)
                ls += __shfl_xor_sync(0xffffffffu, ls, off);
            l_i[i] = l_i[i] * corr[i] + ls;
            m_i[i] = m_new;
        }

        // Publish P packed as row-pairs: Ps2[n][m/2]
#pragma unroll
        for (int j = 0; j < 4; j++)
#pragma unroll
            for (int i2 = 0; i2 < 4; i2++)
                Ps2[(tx * 4 + j) * P2_STRIDE + ty * 4 + i2] =
                    pack2(s[2 * i2][j], s[2 * i2 + 1][j]);

        // Rescale O accumulators by packed corr
#pragma unroll
        for (int i2 = 0; i2 < 4; i2++) {
            u64 c2 = pack2(corr[2 * i2], corr[2 * i2 + 1]);
#pragma unroll
            for (int j = 0; j < 4; j++) mul2(o2[i2][j], c2);
        }
        __syncthreads();   // Ps2 visible to all

        // O += P @ V  (64x64x64)
#pragma unroll 4
        for (int n = 0; n < 64; n++) {
            u64 pp[4];
#pragma unroll
            for (int i2 = 0; i2 < 4; i2++)
                pp[i2] = Ps2[n * P2_STRIDE + ty * 4 + i2];
            float4 v4 = *(const float4*)&Vs[n * 64 + tx * 4];
            u64 vr[4];
            vr[0] = rep2(v4.x); vr[1] = rep2(v4.y);
            vr[2] = rep2(v4.z); vr[3] = rep2(v4.w);
#pragma unroll
            for (int i2 = 0; i2 < 4; i2++)
#pragma unroll
                for (int j = 0; j < 4; j++)
                    fma2(o2[i2][j], pp[i2], vr[j]);
        }
    }

    // Epilogue: normalize, write ctx in [B][S][DIM]
    const int b = bh >> 4;
    const int h = bh & 15;
#pragma unroll
    for (int i2 = 0; i2 < 4; i2++) {
#pragma unroll
        for (int half = 0; half < 2; half++) {
            const int i = 2 * i2 + half;
            const float inv = 1.0f / l_i[i];
            const int q = q0 + ty * 8 + i;
            float4 v4;
            v4.x = (half ? hi2(o2[i2][0]) : lo2(o2[i2][0])) * inv;
            v4.y = (half ? hi2(o2[i2][1]) : lo2(o2[i2][1])) * inv;
            v4.z = (half ? hi2(o2[i2][2]) : lo2(o2[i2][2])) * inv;
            v4.w = (half ? hi2(o2[i2][3]) : lo2(o2[i2][3])) * inv;
            *(float4*)&g_ctx[((size_t)(b * SEQ + q)) * DIM + h * HD + tx * 4] = v4;
        }
    }
}

// ---------------------------------------------------------------------------
// Kernel 3: output projection (same FFMA2 SGEMM, plain output)
// ---------------------------------------------------------------------------
__global__ void __launch_bounds__(256, 2) out_gemm_kernel(
    const float* __restrict__ Wo, const float* __restrict__ bo,
    float* __restrict__ out)
{
    const int K = DIM, N = DIM;
    __shared__ float As[2][BK][128];
    __shared__ float Bs[2][BK][128];

    const int tid = threadIdx.x;
    const int m0 = blockIdx.y * 128;
    const int n0 = blockIdx.x * 128;
    const int tx = tid & 15;
    const int ty = tid >> 4;

    const int arow = tid >> 1;
    const int ak4  = (tid & 1) * 4;
    const int brow = tid >> 5;
    const int bcol = (tid & 31) * 4;

    const float* Aptr = g_ctx + (size_t)(m0 + arow) * K + ak4;
    const float* Bptr = Wo + (size_t)brow * N + n0 + bcol;

    u64 acc[8][4];
#pragma unroll
    for (int i = 0; i < 8; i++)
#pragma unroll
        for (int j = 0; j < 4; j++) acc[i][j] = 0ull;

    float4 av = *(const float4*)Aptr;
    float4 bw = *(const float4*)Bptr;
    As[0][ak4 + 0][arow] = av.x;
    As[0][ak4 + 1][arow] = av.y;
    As[0][ak4 + 2][arow] = av.z;
    As[0][ak4 + 3][arow] = av.w;
    *(float4*)&Bs[0][brow][bcol] = bw;
    __syncthreads();

    int buf = 0;
    for (int k0 = 0; k0 < K; k0 += BK) {
        const bool more = (k0 + BK) < K;
        if (more) {
            av = *(const float4*)(Aptr + k0 + BK);
            bw = *(const float4*)(Bptr + (size_t)(k0 + BK) * N);
        }

#pragma unroll
        for (int kk = 0; kk < BK; kk++) {
            float4 a0 = *(const float4*)&As[buf][kk][ty * 4];
            float4 a1 = *(const float4*)&As[buf][kk][64 + ty * 4];
            u64 b2[4];
            b2[0] = *(const u64*)&Bs[buf][kk][tx * 4];
            b2[1] = *(const u64*)&Bs[buf][kk][tx * 4 + 2];
            b2[2] = *(const u64*)&Bs[buf][kk][64 + tx * 4];
            b2[3] = *(const u64*)&Bs[buf][kk][64 + tx * 4 + 2];
            u64 ar[8];
            ar[0] = rep2(a0.x); ar[1] = rep2(a0.y);
            ar[2] = rep2(a0.z); ar[3] = rep2(a0.w);
            ar[4] = rep2(a1.x); ar[5] = rep2(a1.y);
            ar[6] = rep2(a1.z); ar[7] = rep2(a1.w);
#pragma unroll
            for (int i = 0; i < 8; i++)
#pragma unroll
                for (int j = 0; j < 4; j++)
                    fma2(acc[i][j], ar[i], b2[j]);
        }

        if (more) {
            As[buf ^ 1][ak4 + 0][arow] = av.x;
            As[buf ^ 1][ak4 + 1][arow] = av.y;
            As[buf ^ 1][ak4 + 2][arow] = av.z;
            As[buf ^ 1][ak4 + 3][arow] = av.w;
            *(float4*)&Bs[buf ^ 1][brow][bcol] = bw;
        }
        __syncthreads();
        buf ^= 1;
    }

    const int c0 = n0 + tx * 4;
    float4 bb0 = *(const float4*)&bo[c0];
    float4 bb1 = *(const float4*)&bo[c0 + 64];

#pragma unroll
    for (int g = 0; g < 2; g++) {
#pragma unroll
        for (int i = 0; i < 4; i++) {
            const int ii = g * 4 + i;
            const int m = m0 + g * 64 + ty * 4 + i;
            float4 v0, v1;
            v0.x = lo2(acc[ii][0]) + bb0.x; v0.y = hi2(acc[ii][0]) + bb0.y;
            v0.z = lo2(acc[ii][1]) + bb0.z; v0.w = hi2(acc[ii][1]) + bb0.w;
            v1.x = lo2(acc[ii][2]) + bb1.x; v1.y = hi2(acc[ii][2]) + bb1.y;
            v1.z = lo2(acc[ii][3]) + bb1.z; v1.w = hi2(acc[ii][3]) + bb1.w;
            *(float4*)(out + (size_t)m * N + c0)      = v0;
            *(float4*)(out + (size_t)m * N + c0 + 64) = v1;
        }
    }
}

// ---------------------------------------------------------------------------
// Launch
// ---------------------------------------------------------------------------
extern "C" void kernel_launch(void* const* d_in, const int* in_sizes, int n_in,
                              void* d_out, int out_size)
{
    (void)in_sizes; (void)n_in; (void)out_size;
    const float* x  = (const float*)d_in[0];
    const float* Wq = (const float*)d_in[1];
    const float* bq = (const float*)d_in[2];
    const float* Wk = (const float*)d_in[3];
    const float* bk = (const float*)d_in[4];
    const float* Wv = (const float*)d_in[5];
    const float* bv = (const float*)d_in[6];
    const float* Wo = (const float*)d_in[7];
    const float* bo = (const float*)d_in[8];
    float* out = (float*)d_out;

    cudaFuncSetAttribute(attn_kernel,
                         cudaFuncAttributeMaxDynamicSharedMemorySize, ATTN_SMEM);

    dim3 gq(DIM / 128, MROWS / 128, 3);         // (8, 32, 3)
    qkv_gemm_kernel<<<gq, 256>>>(x, Wq, bq, Wk, bk, Wv, bv);

    dim3 ga(SEQ / 64, BATCH * HEADS);           // (32, 32)
    attn_kernel<<<ga, 128, ATTN_SMEM>>>();

    dim3 go(DIM / 128, MROWS / 128);            // (8, 32)
    out_gemm_kernel<<<go, 256>>>(Wo, bo, out);
}

// round 10
// speedup vs baseline: 1.2282x; 1.0008x over previous
#include <cuda_runtime.h>
#include <cstdint>

// Problem constants
#define BATCH 2
#define SEQ   2048
#define DIM   1024
#define HEADS 16
#define HD    64
#define MROWS (BATCH * SEQ)      // 4096

typedef unsigned long long u64;

// ---------------------------------------------------------------------------
// Packed fp32x2 helpers (Blackwell FFMA2 — ptxas never emits this from C++)
// ---------------------------------------------------------------------------
__device__ __forceinline__ u64 rep2(float x) {
    u64 r;
    asm("mov.b64 %0, {%1, %1};" : "=l"(r) : "r"(__float_as_uint(x)));
    return r;
}
__device__ __forceinline__ u64 pack2(float lo, float hi) {
    u64 r;
    asm("mov.b64 %0, {%1, %2};" : "=l"(r) : "r"(__float_as_uint(lo)), "r"(__float_as_uint(hi)));
    return r;
}
__device__ __forceinline__ void fma2(u64& d, u64 a, u64 b) {
    asm("fma.rn.f32x2 %0, %1, %2, %0;" : "+l"(d) : "l"(a), "l"(b));
}
__device__ __forceinline__ void mul2(u64& d, u64 a) {
    asm("mul.rn.f32x2 %0, %0, %1;" : "+l"(d) : "l"(a));
}
__device__ __forceinline__ float lo2(u64 v) { return __uint_as_float((unsigned)(v & 0xffffffffull)); }
__device__ __forceinline__ float hi2(u64 v) { return __uint_as_float((unsigned)(v >> 32)); }

// ---------------------------------------------------------------------------
// Scratch (device globals; no allocation allowed)
// q/k/v stored as [B*H][S][HD]; ctx as [B][S][DIM]
// ---------------------------------------------------------------------------
__device__ float g_q[BATCH * HEADS * SEQ * HD];
__device__ float g_k[BATCH * HEADS * SEQ * HD];
__device__ float g_v[BATCH * HEADS * SEQ * HD];
__device__ float g_ctx[BATCH * SEQ * DIM];

// ---------------------------------------------------------------------------
// Kernel 1: fused QKV projection, FFMA2 + double-buffered smem.
// 128x128 tile, BK=8, 256 threads. Micro-tile: rows {ty*4, 64+ty*4} x
// cols {tx*4, 64+tx*4}; cols packed as f32x2 pairs, rows replicated.
// ---------------------------------------------------------------------------
#define BK 8
__global__ void __launch_bounds__(256, 2) qkv_gemm_kernel(
    const float* __restrict__ X,
    const float* __restrict__ Wq, const float* __restrict__ bq,
    const float* __restrict__ Wk, const float* __restrict__ bk,
    const float* __restrict__ Wv, const float* __restrict__ bv)
{
    const int K = DIM, N = DIM;
    const float* W; const float* bias; float* dst;
    if (blockIdx.z == 0)      { W = Wq; bias = bq; dst = g_q; }
    else if (blockIdx.z == 1) { W = Wk; bias = bk; dst = g_k; }
    else                      { W = Wv; bias = bv; dst = g_v; }

    __shared__ float As[2][BK][128];   // transposed: As[k][m]
    __shared__ float Bs[2][BK][128];   // Bs[k][n]

    const int tid = threadIdx.x;
    const int m0 = blockIdx.y * 128;
    const int n0 = blockIdx.x * 128;
    const int tx = tid & 15;
    const int ty = tid >> 4;

    const int arow = tid >> 1;
    const int ak4  = (tid & 1) * 4;
    const int brow = tid >> 5;
    const int bcol = (tid & 31) * 4;

    const float* Aptr = X + (size_t)(m0 + arow) * K + ak4;
    const float* Bptr = W + (size_t)brow * N + n0 + bcol;

    u64 acc[8][4];
#pragma unroll
    for (int i = 0; i < 8; i++)
#pragma unroll
        for (int j = 0; j < 4; j++) acc[i][j] = 0ull;

    // Prologue: load tile 0
    float4 av = *(const float4*)Aptr;
    float4 bw = *(const float4*)Bptr;
    As[0][ak4 + 0][arow] = av.x;
    As[0][ak4 + 1][arow] = av.y;
    As[0][ak4 + 2][arow] = av.z;
    As[0][ak4 + 3][arow] = av.w;
    *(float4*)&Bs[0][brow][bcol] = bw;
    __syncthreads();

    int buf = 0;
    for (int k0 = 0; k0 < K; k0 += BK) {
        const bool more = (k0 + BK) < K;
        if (more) {
            av = *(const float4*)(Aptr + k0 + BK);
            bw = *(const float4*)(Bptr + (size_t)(k0 + BK) * N);
        }

#pragma unroll
        for (int kk = 0; kk < BK; kk++) {
            float4 a0 = *(const float4*)&As[buf][kk][ty * 4];
            float4 a1 = *(const float4*)&As[buf][kk][64 + ty * 4];
            u64 b2[4];
            b2[0] = *(const u64*)&Bs[buf][kk][tx * 4];
            b2[1] = *(const u64*)&Bs[buf][kk][tx * 4 + 2];
            b2[2] = *(const u64*)&Bs[buf][kk][64 + tx * 4];
            b2[3] = *(const u64*)&Bs[buf][kk][64 + tx * 4 + 2];
            u64 ar[8];
            ar[0] = rep2(a0.x); ar[1] = rep2(a0.y);
            ar[2] = rep2(a0.z); ar[3] = rep2(a0.w);
            ar[4] = rep2(a1.x); ar[5] = rep2(a1.y);
            ar[6] = rep2(a1.z); ar[7] = rep2(a1.w);
#pragma unroll
            for (int i = 0; i < 8; i++)
#pragma unroll
                for (int j = 0; j < 4; j++)
                    fma2(acc[i][j], ar[i], b2[j]);
        }

        if (more) {
            As[buf ^ 1][ak4 + 0][arow] = av.x;
            As[buf ^ 1][ak4 + 1][arow] = av.y;
            As[buf ^ 1][ak4 + 2][arow] = av.z;
            As[buf ^ 1][ak4 + 3][arow] = av.w;
            *(float4*)&Bs[buf ^ 1][brow][bcol] = bw;
        }
        __syncthreads();
        buf ^= 1;
    }

    // Epilogue: add bias, scatter to [B*H][S][HD].
    const int c0 = n0 + tx * 4;               // first col of group 0 (4-aligned, within one head)
    const int h0 = c0 >> 6;
    const int cc = c0 & 63;
    float4 bb0 = *(const float4*)&bias[c0];
    float4 bb1 = *(const float4*)&bias[c0 + 64];

#pragma unroll
    for (int g = 0; g < 2; g++) {
#pragma unroll
        for (int i = 0; i < 4; i++) {
            const int ii = g * 4 + i;
            const int m = m0 + g * 64 + ty * 4 + i;
            const int b = m >> 11;
            const int s = m & (SEQ - 1);
            float4 v0, v1;
            v0.x = lo2(acc[ii][0]) + bb0.x; v0.y = hi2(acc[ii][0]) + bb0.y;
            v0.z = lo2(acc[ii][1]) + bb0.z; v0.w = hi2(acc[ii][1]) + bb0.w;
            v1.x = lo2(acc[ii][2]) + bb1.x; v1.y = hi2(acc[ii][2]) + bb1.y;
            v1.z = lo2(acc[ii][3]) + bb1.z; v1.w = hi2(acc[ii][3]) + bb1.w;
            *(float4*)(dst + (((size_t)(b * HEADS + h0)     * SEQ + s) * HD + cc)) = v0;
            *(float4*)(dst + (((size_t)(b * HEADS + h0 + 1) * SEQ + s) * HD + cc)) = v1;
        }
    }
}

// ---------------------------------------------------------------------------
// Kernel 2: causal flash attention, fp32 online softmax, FFMA2 inner GEMMs.
// Grid: (S/64, B*H); block 128.  BM=64, BN=64, HD=64.
// Row-pairs packed as f32x2 (acc pairs rows 2i2/2i2+1), cols replicated.
// ---------------------------------------------------------------------------
#define QK_STRIDE 68
#define P2_STRIDE 33   // u64 stride for packed P
#define ATTN_SMEM ((64 * QK_STRIDE * 2 + 64 * 64) * 4 + 64 * P2_STRIDE * 8)

__global__ void __launch_bounds__(128, 3) attn_kernel()
{
    extern __shared__ float sm[];
    float* Qs = sm;                           // [d][m] stride 68
    float* Ks = Qs + 64 * QK_STRIDE;          // [d][n] stride 68
    float* Vs = Ks + 64 * QK_STRIDE;          // [n][d] stride 64
    u64*   Ps2 = (u64*)(Vs + 64 * 64);        // [n][m/2] stride 33 (8B aligned)

    const int bh = blockIdx.y;                // 0..31
    // Heaviest causal tiles first (better tail behavior)
    const int q0 = (gridDim.x - 1 - blockIdx.x) * 64;
    const float* qptr = g_q + (size_t)bh * SEQ * HD;
    const float* kptr = g_k + (size_t)bh * SEQ * HD;
    const float* vptr = g_v + (size_t)bh * SEQ * HD;

    const int tid = threadIdx.x;
    const int tx = tid & 15;                  // 16 col groups of 4
    const int ty = tid >> 4;                  // 8 row groups of 8

    // Load Q tile transposed into Qs[d][m]
    for (int idx = tid; idx < 64 * 16; idx += 128) {
        int m  = idx >> 4;
        int d4 = (idx & 15) * 4;
        float4 v4 = *(const float4*)(qptr + (size_t)(q0 + m) * HD + d4);
        Qs[(d4 + 0) * QK_STRIDE + m] = v4.x;
        Qs[(d4 + 1) * QK_STRIDE + m] = v4.y;
        Qs[(d4 + 2) * QK_STRIDE + m] = v4.z;
        Qs[(d4 + 3) * QK_STRIDE + m] = v4.w;
    }

    float m_i[8], l_i[8];
    u64 o2[4][4];
#pragma unroll
    for (int i = 0; i < 8; i++) { m_i[i] = -1e30f; l_i[i] = 0.0f; }
#pragma unroll
    for (int i2 = 0; i2 < 4; i2++)
#pragma unroll
        for (int j = 0; j < 4; j++) o2[i2][j] = 0ull;

    const int ntiles = q0 / 64 + 1;           // causal: skip future tiles
    const float scale = 0.125f;               // 1/sqrt(64)

    for (int t = 0; t < ntiles; t++) {
        const int n0 = t * 64;
        __syncthreads();   // protect Ks/Vs from previous iter's readers (and Qs on t=0)
        for (int idx = tid; idx < 64 * 16; idx += 128) {
            int n  = idx >> 4;
            int d4 = (idx & 15) * 4;
            float4 kv = *(const float4*)(kptr + (size_t)(n0 + n) * HD + d4);
            Ks[(d4 + 0) * QK_STRIDE + n] = kv.x;
            Ks[(d4 + 1) * QK_STRIDE + n] = kv.y;
            Ks[(d4 + 2) * QK_STRIDE + n] = kv.z;
            Ks[(d4 + 3) * QK_STRIDE + n] = kv.w;
            float4 vv = *(const float4*)(vptr + (size_t)(n0 + n) * HD + d4);
            *(float4*)&Vs[n * 64 + d4] = vv;
        }
        __syncthreads();

        // S = Q @ K^T  (64x64x64): rows packed in pairs, cols replicated
        u64 s2[4][4];
#pragma unroll
        for (int i2 = 0; i2 < 4; i2++)
#pragma unroll
            for (int j = 0; j < 4; j++) s2[i2][j] = 0ull;

#pragma unroll 8
        for (int kk = 0; kk < 64; kk++) {
            u64 ap[4];
#pragma unroll
            for (int i2 = 0; i2 < 4; i2++)
                ap[i2] = *(const u64*)&Qs[kk * QK_STRIDE + ty * 8 + 2 * i2];
            float4 b4 = *(const float4*)&Ks[kk * QK_STRIDE + tx * 4];
            u64 br[4];
            br[0] = rep2(b4.x); br[1] = rep2(b4.y);
            br[2] = rep2(b4.z); br[3] = rep2(b4.w);
#pragma unroll
            for (int i2 = 0; i2 < 4; i2++)
#pragma unroll
                for (int j = 0; j < 4; j++)
                    fma2(s2[i2][j], ap[i2], br[j]);
        }

        // Unpack, scale + causal mask (exactly -10000, matching reference)
        float s[8][4];
#pragma unroll
        for (int i2 = 0; i2 < 4; i2++)
#pragma unroll
            for (int j = 0; j < 4; j++) {
                s[2 * i2 + 0][j] = lo2(s2[i2][j]);
                s[2 * i2 + 1][j] = hi2(s2[i2][j]);
            }
#pragma unroll
        for (int i = 0; i < 8; i++) {
            int q = q0 + ty * 8 + i;
#pragma unroll
            for (int j = 0; j < 4; j++) {
                int kc = n0 + tx * 4 + j;
                s[i][j] = (kc <= q) ? s[i][j] * scale : -10000.0f;
            }
        }

        // Online softmax per row (rows shared by 16 lanes with same ty)
        float corr[8];
#pragma unroll
        for (int i = 0; i < 8; i++) {
            float mx = fmaxf(fmaxf(s[i][0], s[i][1]), fmaxf(s[i][2], s[i][3]));
#pragma unroll
            for (int off = 8; off >= 1; off >>= 1)
                mx = fmaxf(mx, __shfl_xor_sync(0xffffffffu, mx, off));
            float m_new = fmaxf(m_i[i], mx);
            corr[i] = __expf(m_i[i] - m_new);
            float ls = 0.0f;
#pragma unroll
            for (int j = 0; j < 4; j++) {
                float p = __expf(s[i][j] - m_new);
                s[i][j] = p;                  // reuse s as P
                ls += p;
            }
#pragma unroll
            for (int off = 8; off >= 1; off >>= 1)
                ls += __shfl_xor_sync(0xffffffffu, ls, off);
            l_i[i] = l_i[i] * corr[i] + ls;
            m_i[i] = m_new;
        }

        // Publish P packed as row-pairs: Ps2[n][m/2]
#pragma unroll
        for (int j = 0; j < 4; j++)
#pragma unroll
            for (int i2 = 0; i2 < 4; i2++)
                Ps2[(tx * 4 + j) * P2_STRIDE + ty * 4 + i2] =
                    pack2(s[2 * i2][j], s[2 * i2 + 1][j]);

        // Rescale O accumulators by packed corr
#pragma unroll
        for (int i2 = 0; i2 < 4; i2++) {
            u64 c2 = pack2(corr[2 * i2], corr[2 * i2 + 1]);
#pragma unroll
            for (int j = 0; j < 4; j++) mul2(o2[i2][j], c2);
        }
        __syncthreads();   // Ps2 visible to all

        // O += P @ V  (64x64x64)
#pragma unroll 4
        for (int n = 0; n < 64; n++) {
            u64 pp[4];
#pragma unroll
            for (int i2 = 0; i2 < 4; i2++)
                pp[i2] = Ps2[n * P2_STRIDE + ty * 4 + i2];
            float4 v4 = *(const float4*)&Vs[n * 64 + tx * 4];
            u64 vr[4];
            vr[0] = rep2(v4.x); vr[1] = rep2(v4.y);
            vr[2] = rep2(v4.z); vr[3] = rep2(v4.w);
#pragma unroll
            for (int i2 = 0; i2 < 4; i2++)
#pragma unroll
                for (int j = 0; j < 4; j++)
                    fma2(o2[i2][j], pp[i2], vr[j]);
        }
    }

    // Epilogue: normalize, write ctx in [B][S][DIM]
    const int b = bh >> 4;
    const int h = bh & 15;
#pragma unroll
    for (int i2 = 0; i2 < 4; i2++) {
#pragma unroll
        for (int half = 0; half < 2; half++) {
            const int i = 2 * i2 + half;
            const float inv = 1.0f / l_i[i];
            const int q = q0 + ty * 8 + i;
            float4 v4;
            v4.x = (half ? hi2(o2[i2][0]) : lo2(o2[i2][0])) * inv;
            v4.y = (half ? hi2(o2[i2][1]) : lo2(o2[i2][1])) * inv;
            v4.z = (half ? hi2(o2[i2][2]) : lo2(o2[i2][2])) * inv;
            v4.w = (half ? hi2(o2[i2][3]) : lo2(o2[i2][3])) * inv;
            *(float4*)&g_ctx[((size_t)(b * SEQ + q)) * DIM + h * HD + tx * 4] = v4;
        }
    }
}

// ---------------------------------------------------------------------------
// Kernel 3: output projection (same FFMA2 SGEMM, plain output)
// ---------------------------------------------------------------------------
__global__ void __launch_bounds__(256, 2) out_gemm_kernel(
    const float* __restrict__ Wo, const float* __restrict__ bo,
    float* __restrict__ out)
{
    const int K = DIM, N = DIM;
    __shared__ float As[2][BK][128];
    __shared__ float Bs[2][BK][128];

    const int tid = threadIdx.x;
    const int m0 = blockIdx.y * 128;
    const int n0 = blockIdx.x * 128;
    const int tx = tid & 15;
    const int ty = tid >> 4;

    const int arow = tid >> 1;
    const int ak4  = (tid & 1) * 4;
    const int brow = tid >> 5;
    const int bcol = (tid & 31) * 4;

    const float* Aptr = g_ctx + (size_t)(m0 + arow) * K + ak4;
    const float* Bptr = Wo + (size_t)brow * N + n0 + bcol;

    u64 acc[8][4];
#pragma unroll
    for (int i = 0; i < 8; i++)
#pragma unroll
        for (int j = 0; j < 4; j++) acc[i][j] = 0ull;

    float4 av = *(const float4*)Aptr;
    float4 bw = *(const float4*)Bptr;
    As[0][ak4 + 0][arow] = av.x;
    As[0][ak4 + 1][arow] = av.y;
    As[0][ak4 + 2][arow] = av.z;
    As[0][ak4 + 3][arow] = av.w;
    *(float4*)&Bs[0][brow][bcol] = bw;
    __syncthreads();

    int buf = 0;
    for (int k0 = 0; k0 < K; k0 += BK) {
        const bool more = (k0 + BK) < K;
        if (more) {
            av = *(const float4*)(Aptr + k0 + BK);
            bw = *(const float4*)(Bptr + (size_t)(k0 + BK) * N);
        }

#pragma unroll
        for (int kk = 0; kk < BK; kk++) {
            float4 a0 = *(const float4*)&As[buf][kk][ty * 4];
            float4 a1 = *(const float4*)&As[buf][kk][64 + ty * 4];
            u64 b2[4];
            b2[0] = *(const u64*)&Bs[buf][kk][tx * 4];
            b2[1] = *(const u64*)&Bs[buf][kk][tx * 4 + 2];
            b2[2] = *(const u64*)&Bs[buf][kk][64 + tx * 4];
            b2[3] = *(const u64*)&Bs[buf][kk][64 + tx * 4 + 2];
            u64 ar[8];
            ar[0] = rep2(a0.x); ar[1] = rep2(a0.y);
            ar[2] = rep2(a0.z); ar[3] = rep2(a0.w);
            ar[4] = rep2(a1.x); ar[5] = rep2(a1.y);
            ar[6] = rep2(a1.z); ar[7] = rep2(a1.w);
#pragma unroll
            for (int i = 0; i < 8; i++)
#pragma unroll
                for (int j = 0; j < 4; j++)
                    fma2(acc[i][j], ar[i], b2[j]);
        }

        if (more) {
            As[buf ^ 1][ak4 + 0][arow] = av.x;
            As[buf ^ 1][ak4 + 1][arow] = av.y;
            As[buf ^ 1][ak4 + 2][arow] = av.z;
            As[buf ^ 1][ak4 + 3][arow] = av.w;
            *(float4*)&Bs[buf ^ 1][brow][bcol] = bw;
        }
        __syncthreads();
        buf ^= 1;
    }

    const int c0 = n0 + tx * 4;
    float4 bb0 = *(const float4*)&bo[c0];
    float4 bb1 = *(const float4*)&bo[c0 + 64];

#pragma unroll
    for (int g = 0; g < 2; g++) {
#pragma unroll
        for (int i = 0; i < 4; i++) {
            const int ii = g * 4 + i;
            const int m = m0 + g * 64 + ty * 4 + i;
            float4 v0, v1;
            v0.x = lo2(acc[ii][0]) + bb0.x; v0.y = hi2(acc[ii][0]) + bb0.y;
            v0.z = lo2(acc[ii][1]) + bb0.z; v0.w = hi2(acc[ii][1]) + bb0.w;
            v1.x = lo2(acc[ii][2]) + bb1.x; v1.y = hi2(acc[ii][2]) + bb1.y;
            v1.z = lo2(acc[ii][3]) + bb1.z; v1.w = hi2(acc[ii][3]) + bb1.w;
            *(float4*)(out + (size_t)m * N + c0)      = v0;
            *(float4*)(out + (size_t)m * N + c0 + 64) = v1;
        }
    }
}

// ---------------------------------------------------------------------------
// Launch
// ---------------------------------------------------------------------------
extern "C" void kernel_launch(void* const* d_in, const int* in_sizes, int n_in,
                              void* d_out, int out_size)
{
    (void)in_sizes; (void)n_in; (void)out_size;
    const float* x  = (const float*)d_in[0];
    const float* Wq = (const float*)d_in[1];
    const float* bq = (const float*)d_in[2];
    const float* Wk = (const float*)d_in[3];
    const float* bk = (const float*)d_in[4];
    const float* Wv = (const float*)d_in[5];
    const float* bv = (const float*)d_in[6];
    const float* Wo = (const float*)d_in[7];
    const float* bo = (const float*)d_in[8];
    float* out = (float*)d_out;

    cudaFuncSetAttribute(attn_kernel,
                         cudaFuncAttributeMaxDynamicSharedMemorySize, ATTN_SMEM);

    dim3 gq(DIM / 128, MROWS / 128, 3);         // (8, 32, 3)
    qkv_gemm_kernel<<<gq, 256>>>(x, Wq, bq, Wk, bk, Wv, bv);

    dim3 ga(SEQ / 64, BATCH * HEADS);           // (32, 32)
    attn_kernel<<<ga, 128, ATTN_SMEM>>>();

    dim3 go(DIM / 128, MROWS / 128);            // (8, 32)
    out_gemm_kernel<<<go, 256>>>(Wo, bo, out);
}